// round 12
// baseline (speedup 1.0000x reference)
#include <cuda_runtime.h>
#include <math.h>

#define BB 64
#define CIN 256
#define COUT 256
#define HH 64
#define WW 64
#define NB 8
#define HID 128
#define HWPIX 4096

#define TILE_H 8
#define CONV_THREADS 128
#define XROWS 10                 /* TILE_H + 2 halo */
#define XCOLS 66                 /* 64 + 2 halo (logical) */
#define XSTRIDE 68               /* padded row stride in floats */
#define XT_ELEMS (XROWS * XCOLS) /* 660 */
#define NLD 6
#define CHALF 64                 /* channels per filter-smem pass */
#define FSD_ELEMS (CHALF * 9 * NB) /* 4608 float2 = 36 KB */

// -------- scratch (no cudaMalloc allowed) --------
__device__ __align__(16) float2 g_fdup[CIN * 9 * NB];   // [(c*9+tap)*8+n] = (f,f)
__device__ __align__(16) float  g_pp[BB * CIN * 32];    // per-(htile,warp) pool partials
__device__ __align__(16) float  g_mix[BB * COUT * NB];
__device__ __align__(16) float  g_y[(size_t)BB * NB * HWPIX];

// -------- packed f32x2 helpers (sm_103a) --------
static __device__ __forceinline__ unsigned long long pk2(float lo, float hi) {
    unsigned long long r;
    asm("mov.b64 %0, {%1, %2};" : "=l"(r) : "f"(lo), "f"(hi));
    return r;
}
static __device__ __forceinline__ void upk2(unsigned long long v, float &lo, float &hi) {
    asm("mov.b64 {%0, %1}, %2;" : "=f"(lo), "=f"(hi) : "l"(v));
}
static __device__ __forceinline__ unsigned long long fma2(
    unsigned long long a, unsigned long long b, unsigned long long c) {
    unsigned long long d;
    asm("fma.rn.f32x2 %0, %1, %2, %3;" : "=l"(d) : "l"(a), "l"(b), "l"(c));
    return d;
}
static __device__ __forceinline__ unsigned long long lds64(const float2* p) {
    unsigned long long r;
    asm("ld.shared.b64 %0, [%1];" : "=l"(r) : "l"((unsigned long long)__cvta_generic_to_shared(p)));
    return r;
}

// -------- kernel 0: pre-duplicate filters (f,f) for broadcast LDS.64 --------
__global__ void prep_kernel(const float* __restrict__ bf) {
    int i = blockIdx.x * blockDim.x + threadIdx.x;
    if (i < CIN * 9 * NB) {
        int n = i & 7, tap = (i >> 3) % 9, c = i / 72;
        float v = bf[n * 2304 + c * 9 + tap];
        g_fdup[i] = make_float2(v, v);
    }
}

// -------- kernel 1: fused 3x3 conv (8 filters) + pool partials --------
// Grid: 64 b * 8 htiles = 512 CTAs, 128 threads.
// Warp w owns output rows 2w, 2w+1; lane l owns pixel PAIR (2l, 2l+1).
// fma2 lanes = pixel pair; filter operand = duplicated (f,f) broadcast LDS.64.
__global__ __launch_bounds__(CONV_THREADS)
void conv_pool_kernel(const float* __restrict__ x) {
    __shared__ float2 fsd[FSD_ELEMS];            // 36 KB duplicated filters (64-ch pass)
    __shared__ float  xs[2][XROWS * XSTRIDE];    // f32 tile, double-buffered (5.3 KB)

    const int t  = threadIdx.x;
    const int w  = t >> 5;
    const int l  = t & 31;
    const int b  = blockIdx.x >> 3;
    const int ht = blockIdx.x & 7;
    const int h0 = ht * TILE_H;

    // per-thread staging slots for the 660-elem logical tile
    int  offk[NLD], sidx[NLD];
    bool vk[NLD], pmk[NLD], ik[NLD];
#pragma unroll
    for (int k = 0; k < NLD; k++) {
        int idx = t + k * CONV_THREADS;
        vk[k] = false; pmk[k] = false; ik[k] = false; offk[k] = 0; sidx[k] = 0;
        if (idx < XT_ELEMS) {
            ik[k] = true;
            int row = idx / XCOLS, col = idx % XCOLS;
            sidx[k] = row * XSTRIDE + col;
            int gh = h0 - 1 + row, gw = col - 1;
            if (gh >= 0 && gh < HH && gw >= 0 && gw < WW) {
                vk[k]  = true;
                offk[k] = gh * WW + gw;
                pmk[k] = (row >= 1 && row <= TILE_H && col >= 1 && col <= WW);
            }
        }
    }
    const float* xb = x + (size_t)b * CIN * HWPIX;

    // prefetch channel 0
    float ld[NLD];
#pragma unroll
    for (int k = 0; k < NLD; k++) ld[k] = vk[k] ? __ldg(xb + offk[k]) : 0.f;

    unsigned long long acc[NB][2];    // [n][row 0/1] — pixel pair (2l, 2l+1)
#pragma unroll
    for (int n = 0; n < NB; n++) { acc[n][0] = 0ULL; acc[n][1] = 0ULL; }

    for (int c = 0; c < CIN; c++) {
        const int cl  = c & (CHALF - 1);
        const int buf = c & 1;

        // stage duplicated filters for this 64-channel pass (coalesced copy)
        if (cl == 0) {
            if (c != 0) __syncthreads();          // readers of old fsd done
            const float2* src = g_fdup + c * 9 * NB;
            for (int i = t; i < FSD_ELEMS; i += CONV_THREADS) fsd[i] = src[i];
        }

        // stage x tile + pool partial from registers
        float ps = 0.f;
#pragma unroll
        for (int k = 0; k < NLD; k++) {
            if (ik[k]) xs[buf][sidx[k]] = ld[k];
            if (pmk[k]) ps += ld[k];
        }
        __syncthreads();

        // pool partial: per-warp direct store (no atomics)
#pragma unroll
        for (int o = 16; o > 0; o >>= 1) ps += __shfl_down_sync(0xffffffffu, ps, o);
        if (l == 0) g_pp[(b * CIN + c) * 32 + ht * 4 + w] = ps;

        // prefetch next channel
        if (c + 1 < CIN) {
            const float* xc = xb + (size_t)(c + 1) * HWPIX;
#pragma unroll
            for (int k = 0; k < NLD; k++) ld[k] = vk[k] ? __ldg(xc + offk[k]) : 0.f;
        }

        // compute: per dy: 8 conflict-free LDS.32 + 6 pk2 + 24 f LDS.64 + 48 fma2
        const float2* F = fsd + cl * 72;
        const float*  X = xs[buf];
#pragma unroll
        for (int dy = 0; dy < 3; dy++) {
            const float* xr0 = X + (2 * w + dy) * XSTRIDE + 2 * l;
            const float* xr1 = xr0 + XSTRIDE;
            float a0 = xr0[0], a1 = xr0[1], a2 = xr0[2], a3 = xr0[3];
            float b0 = xr1[0], b1 = xr1[1], b2 = xr1[2], b3 = xr1[3];
            unsigned long long PA[3] = { pk2(a0, a1), pk2(a1, a2), pk2(a2, a3) };
            unsigned long long PB[3] = { pk2(b0, b1), pk2(b1, b2), pk2(b2, b3) };
#pragma unroll
            for (int dx = 0; dx < 3; dx++) {
                const float2* fp = F + (dy * 3 + dx) * NB;
#pragma unroll
                for (int n = 0; n < NB; n++) {
                    unsigned long long f = lds64(fp + n);
                    acc[n][0] = fma2(PA[dx], f, acc[n][0]);
                    acc[n][1] = fma2(PB[dx], f, acc[n][1]);
                }
            }
        }
    }

    // epilogue: pixel pairs are lane-contiguous -> coalesced STG.64
#pragma unroll
    for (int n = 0; n < NB; n++) {
#pragma unroll
        for (int row = 0; row < 2; row++) {
            float lo, hi;
            upk2(acc[n][row], lo, hi);
            float* yp = g_y + ((size_t)(b * NB + n) * HWPIX) + (h0 + 2 * w + row) * WW + 2 * l;
            *(float2*)yp = make_float2(lo, hi);
        }
    }
}

// -------- kernel 2: attention MLP + softmax (warp-cooperative, coalesced) --------
__global__ __launch_bounds__(256)
void mlp_kernel(const float* __restrict__ w1, const float* __restrict__ b1,
                const float* __restrict__ w2, const float* __restrict__ b2) {
    __shared__ float psm[CIN];
    __shared__ float hs[HID];
    __shared__ float raw[COUT * NB];
    const int b = blockIdx.x, t = threadIdx.x;
    const int w = t >> 5, l = t & 31;

    // pooled[c] = sum of 32 partials / 4096
    {
        const float4* pp = (const float4*)(g_pp + (size_t)(b * CIN + t) * 32);
        float s = 0.f;
#pragma unroll
        for (int j = 0; j < 8; j++) {
            float4 v = pp[j];
            s += v.x + v.y + v.z + v.w;
        }
        psm[t] = s * (1.f / (float)HWPIX);
    }
    __syncthreads();

    // h = relu(w1 @ pooled + b1): warp-cooperative rows
#pragma unroll
    for (int i = 0; i < HID / 8; i++) {
        int j = w * (HID / 8) + i;
        float4 wa = *(const float4*)(w1 + (size_t)j * CIN + 8 * l);
        float4 wbv = *(const float4*)(w1 + (size_t)j * CIN + 8 * l + 4);
        const float4 pa = *(const float4*)(psm + 8 * l);
        const float4 pb = *(const float4*)(psm + 8 * l + 4);
        float s = wa.x * pa.x + wa.y * pa.y + wa.z * pa.z + wa.w * pa.w
                + wbv.x * pb.x + wbv.y * pb.y + wbv.z * pb.z + wbv.w * pb.w;
#pragma unroll
        for (int o = 16; o > 0; o >>= 1) s += __shfl_xor_sync(0xffffffffu, s, o);
        if (l == 0) hs[j] = fmaxf(s + b1[j], 0.f);
    }
    __syncthreads();

    // raw = w2 @ h + b2: warp per row (coalesced 512B rows)
#pragma unroll 2
    for (int i = 0; i < (COUT * NB) / 8; i++) {
        int row = w * ((COUT * NB) / 8) + i;
        float4 wv = *(const float4*)(w2 + (size_t)row * HID + 4 * l);
        const float4 hv = *(const float4*)(hs + 4 * l);
        float s = wv.x * hv.x + wv.y * hv.y + wv.z * hv.z + wv.w * hv.w;
#pragma unroll
        for (int o = 16; o > 0; o >>= 1) s += __shfl_xor_sync(0xffffffffu, s, o);
        if (l == 0) raw[row] = s + b2[row];
    }
    __syncthreads();

    // softmax over n for o = t
    float v[NB];
#pragma unroll
    for (int n = 0; n < NB; n++) v[n] = raw[t * NB + n];
    float m = v[0];
#pragma unroll
    for (int n = 1; n < NB; n++) m = fmaxf(m, v[n]);
    float e[NB], s = 0.f;
#pragma unroll
    for (int n = 0; n < NB; n++) { e[n] = expf(v[n] - m); s += e[n]; }
    float inv = 1.f / s;
#pragma unroll
    for (int n = 0; n < NB; n++) g_mix[b * COUT * NB + t * NB + n] = e[n] * inv;
}

// -------- kernel 3: out[b,o,p] = sum_n mix[b,o,n] * y[b,n,p] --------
// Grid: 64 b * 4 o-quarters * 4 pixel-chunks = 1024 CTAs, 256 threads, 4 px/thread.
__global__ __launch_bounds__(256)
void apply_kernel(float* __restrict__ out) {
    __shared__ __align__(16) float ms[64 * NB];
    const int b  = blockIdx.x >> 4;
    const int oq = (blockIdx.x >> 2) & 3;
    const int t  = threadIdx.x;
    const int p0 = (blockIdx.x & 3) * 1024 + t * 4;

    for (int i = t; i < 64 * NB; i += 256)
        ms[i] = g_mix[b * COUT * NB + oq * 64 * NB + i];
    __syncthreads();

    unsigned long long y2[NB][2];
#pragma unroll
    for (int n = 0; n < NB; n++) {
        float4 v = *(const float4*)(g_y + (size_t)(b * NB + n) * HWPIX + p0);
        y2[n][0] = pk2(v.x, v.y);
        y2[n][1] = pk2(v.z, v.w);
    }

    float* ob = out + ((size_t)b * COUT + oq * 64) * HWPIX + p0;
    for (int o = 0; o < 64; o++) {
        const float4 m0 = *(const float4*)(ms + o * NB);
        const float4 m1 = *(const float4*)(ms + o * NB + 4);
        float mv[8] = {m0.x, m0.y, m0.z, m0.w, m1.x, m1.y, m1.z, m1.w};
        unsigned long long a0 = 0ULL, a1 = 0ULL;
#pragma unroll
        for (int n = 0; n < NB; n++) {
            unsigned long long fb = pk2(mv[n], mv[n]);
            a0 = fma2(y2[n][0], fb, a0);
            a1 = fma2(y2[n][1], fb, a1);
        }
        float o0, o1, o2, o3;
        upk2(a0, o0, o1);
        upk2(a1, o2, o3);
        __stcs((float4*)(ob + (size_t)o * HWPIX), make_float4(o0, o1, o2, o3));
    }
}

extern "C" void kernel_launch(void* const* d_in, const int* in_sizes, int n_in,
                              void* d_out, int out_size) {
    const float* x  = (const float*)d_in[0];
    const float* w1 = (const float*)d_in[1];
    const float* b1 = (const float*)d_in[2];
    const float* w2 = (const float*)d_in[3];
    const float* b2 = (const float*)d_in[4];
    const float* bf = (const float*)d_in[5];
    float* out = (float*)d_out;

    prep_kernel<<<(CIN * 9 * NB + 255) / 256, 256>>>(bf);
    conv_pool_kernel<<<BB * 8, CONV_THREADS>>>(x);
    mlp_kernel<<<BB, 256>>>(w1, b1, w2, b2);
    apply_kernel<<<BB * 16, 256>>>(out);
}

// round 13
// speedup vs baseline: 1.1009x; 1.1009x over previous
#include <cuda_runtime.h>
#include <math.h>

#define BB 64
#define CIN 256
#define COUT 256
#define HH 64
#define WW 64
#define NB 8
#define HID 128
#define HWPIX 4096

#define TILE_H 16
#define CONV_THREADS 128
#define XS_ROWS 18
#define XS_COLS 66
#define XS_ELEMS (XS_ROWS * XS_COLS)   /* 1188 */
#define NLD 10
#define CHALF 128                       /* channels per filter-smem pass */
#define FSD_ELEMS (CHALF * 9 * NB)      /* 9216 float2 = 72 KB */

// -------- scratch (no cudaMalloc allowed) --------
__device__ __align__(16) float2 g_fdup[CIN * 9 * NB];   // [(c*9+tap)*8+n] = (f,f)
__device__ __align__(16) float  g_pp[BB * CIN * 16];    // per-(htile,warp) pool partials
__device__ __align__(16) float  g_mix[BB * COUT * NB];
__device__ __align__(16) float  g_y[(size_t)BB * NB * HWPIX];

// -------- packed f32x2 helpers (sm_103a) --------
static __device__ __forceinline__ unsigned long long pk2(float lo, float hi) {
    unsigned long long r;
    asm("mov.b64 %0, {%1, %2};" : "=l"(r) : "f"(lo), "f"(hi));
    return r;
}
static __device__ __forceinline__ void upk2(unsigned long long v, float &lo, float &hi) {
    asm("mov.b64 {%0, %1}, %2;" : "=f"(lo), "=f"(hi) : "l"(v));
}
static __device__ __forceinline__ unsigned long long fma2(
    unsigned long long a, unsigned long long b, unsigned long long c) {
    unsigned long long d;
    asm("fma.rn.f32x2 %0, %1, %2, %3;" : "=l"(d) : "l"(a), "l"(b), "l"(c));
    return d;
}
static __device__ __forceinline__ unsigned long long lds64(const float2* p) {
    unsigned long long r;
    asm("ld.shared.b64 %0, [%1];" : "=l"(r) : "l"((unsigned long long)__cvta_generic_to_shared(p)));
    return r;
}

// -------- kernel 0: pre-duplicate filters (f,f) for broadcast LDS.64 --------
__global__ void prep_kernel(const float* __restrict__ bf) {
    int i = blockIdx.x * blockDim.x + threadIdx.x;
    if (i < CIN * 9 * NB) {
        int n = i & 7, tap = (i >> 3) % 9, c = i / 72;
        float v = bf[n * 2304 + c * 9 + tap];
        g_fdup[i] = make_float2(v, v);
    }
}

// -------- kernel 1: fused 3x3 conv (8 filters, all 256 ch) + pool partials --------
// R1 structure: 64 b * 4 htiles = 256 CTAs, 128 threads (2 CTAs/SM, single wave).
// Thread t: row r = t>>3 in tile, 8 contiguous px at wbase=(t&7)*8 (4 f32x2 pairs).
// fma2 lanes = pixel pair; filter operand = pre-duplicated (f,f) broadcast LDS.64.
__global__ __launch_bounds__(CONV_THREADS, 2)
void conv_pool_kernel(const float* __restrict__ x) {
    extern __shared__ float smem[];
    float2* fsd = (float2*)smem;                 // [cl][tap][n] dup filters (72 KB)
    float*  xs  = smem + 2 * FSD_ELEMS;          // [18][66] x tile (4.64 KB)

    const int t     = threadIdx.x;
    const int w     = t >> 5;
    const int b     = blockIdx.x >> 2;
    const int ht    = blockIdx.x & 3;
    const int h0    = ht * TILE_H;
    const int r     = t >> 3;
    const int wbase = (t & 7) * 8;

    // per-thread staging slots for the 1188-elem tile
    int  offk[NLD];
    bool vk[NLD], pmk[NLD];
#pragma unroll
    for (int k = 0; k < NLD; k++) {
        int idx = t + k * CONV_THREADS;
        vk[k] = false; pmk[k] = false; offk[k] = 0;
        if (idx < XS_ELEMS) {
            int row = idx / XS_COLS, col = idx % XS_COLS;
            int gh = h0 - 1 + row, gw = col - 1;
            if (gh >= 0 && gh < HH && gw >= 0 && gw < WW) {
                vk[k]  = true;
                offk[k] = gh * WW + gw;
                pmk[k] = (row >= 1 && row <= TILE_H && col >= 1 && col <= WW);
            }
        }
    }
    const float* xb = x + (size_t)b * CIN * HWPIX;

    // prefetch channel 0
    float ld[NLD];
#pragma unroll
    for (int k = 0; k < NLD; k++) ld[k] = vk[k] ? __ldg(xb + offk[k]) : 0.f;

    unsigned long long acc[NB][4];
#pragma unroll
    for (int n = 0; n < NB; n++)
#pragma unroll
        for (int j = 0; j < 4; j++) acc[n][j] = 0ULL;

    for (int c = 0; c < CIN; c++) {
        const int cl = c & (CHALF - 1);

        __syncthreads();   // prior compute finished reading xs (and fsd)

        // stage duplicated filters for this 128-channel pass (overlaps x store)
        if (cl == 0) {
            const float2* src = g_fdup + (size_t)c * 9 * NB;
            for (int i = t; i < FSD_ELEMS; i += CONV_THREADS) fsd[i] = src[i];
        }

        // store x tile + pool partial from registers
        float ps = 0.f;
#pragma unroll
        for (int k = 0; k < NLD; k++) {
            int idx = t + k * CONV_THREADS;
            if (idx < XS_ELEMS) xs[idx] = ld[k];
            if (pmk[k]) ps += ld[k];
        }
        __syncthreads();   // tile (and filters) ready

        // pool partial: per-warp direct store (no atomics)
#pragma unroll
        for (int o = 16; o > 0; o >>= 1) ps += __shfl_down_sync(0xffffffffu, ps, o);
        if ((t & 31) == 0) g_pp[(b * CIN + c) * 16 + ht * 4 + w] = ps;

        // prefetch next channel (hides DRAM latency under FMA phase)
        if (c + 1 < CIN) {
            const float* xc = xb + (size_t)(c + 1) * HWPIX;
#pragma unroll
            for (int k = 0; k < NLD; k++) ld[k] = vk[k] ? __ldg(xc + offk[k]) : 0.f;
        }

        // compute: 3 dy * (10 LDS.32 + 12 pk2 + 24 broadcast f LDS.64 + 96 fma2)
        const float2* fc = fsd + cl * 72;
#pragma unroll
        for (int dy = 0; dy < 3; dy++) {
            float xr[10];
            const float* xrow = xs + (r + dy) * XS_COLS + wbase;
#pragma unroll
            for (int i = 0; i < 10; i++) xr[i] = xrow[i];
            unsigned long long P[3][4];
#pragma unroll
            for (int j = 0; j < 4; j++) {
                P[0][j] = pk2(xr[2 * j],     xr[2 * j + 1]);  // dx = -1
                P[1][j] = pk2(xr[2 * j + 1], xr[2 * j + 2]);  // dx =  0
                P[2][j] = pk2(xr[2 * j + 2], xr[2 * j + 3]);  // dx = +1
            }
#pragma unroll
            for (int dx = 0; dx < 3; dx++) {
                const float2* fp = fc + (dy * 3 + dx) * NB;
#pragma unroll
                for (int n = 0; n < NB; n++) {
                    unsigned long long f = lds64(fp + n);
                    acc[n][0] = fma2(P[dx][0], f, acc[n][0]);
                    acc[n][1] = fma2(P[dx][1], f, acc[n][1]);
                    acc[n][2] = fma2(P[dx][2], f, acc[n][2]);
                    acc[n][3] = fma2(P[dx][3], f, acc[n][3]);
                }
            }
        }
    }

    // write y[b,n,h0+r, wbase..wbase+7] as two float4s
#pragma unroll
    for (int n = 0; n < NB; n++) {
        float v[8];
#pragma unroll
        for (int j = 0; j < 4; j++) upk2(acc[n][j], v[2 * j], v[2 * j + 1]);
        float* yp = g_y + ((size_t)(b * NB + n) * HH + (h0 + r)) * WW + wbase;
        *(float4*)(yp)     = make_float4(v[0], v[1], v[2], v[3]);
        *(float4*)(yp + 4) = make_float4(v[4], v[5], v[6], v[7]);
    }
}

// -------- kernel 2: attention MLP + softmax (warp-cooperative, coalesced) --------
__global__ __launch_bounds__(256)
void mlp_kernel(const float* __restrict__ w1, const float* __restrict__ b1,
                const float* __restrict__ w2, const float* __restrict__ b2) {
    __shared__ float psm[CIN];
    __shared__ float hs[HID];
    __shared__ float raw[COUT * NB];
    const int b = blockIdx.x, t = threadIdx.x;
    const int w = t >> 5, l = t & 31;

    // pooled[c] = sum of 16 partials / 4096
    {
        const float4* pp = (const float4*)(g_pp + (size_t)(b * CIN + t) * 16);
        float s = 0.f;
#pragma unroll
        for (int j = 0; j < 4; j++) {
            float4 v = pp[j];
            s += v.x + v.y + v.z + v.w;
        }
        psm[t] = s * (1.f / (float)HWPIX);
    }
    __syncthreads();

    // h = relu(w1 @ pooled + b1): warp-cooperative rows
#pragma unroll
    for (int i = 0; i < HID / 8; i++) {
        int j = w * (HID / 8) + i;
        float4 wa = *(const float4*)(w1 + (size_t)j * CIN + 8 * l);
        float4 wbv = *(const float4*)(w1 + (size_t)j * CIN + 8 * l + 4);
        const float4 pa = *(const float4*)(psm + 8 * l);
        const float4 pb = *(const float4*)(psm + 8 * l + 4);
        float s = wa.x * pa.x + wa.y * pa.y + wa.z * pa.z + wa.w * pa.w
                + wbv.x * pb.x + wbv.y * pb.y + wbv.z * pb.z + wbv.w * pb.w;
#pragma unroll
        for (int o = 16; o > 0; o >>= 1) s += __shfl_xor_sync(0xffffffffu, s, o);
        if (l == 0) hs[j] = fmaxf(s + b1[j], 0.f);
    }
    __syncthreads();

    // raw = w2 @ h + b2: warp per row (coalesced 512B rows)
#pragma unroll 2
    for (int i = 0; i < (COUT * NB) / 8; i++) {
        int row = w * ((COUT * NB) / 8) + i;
        float4 wv = *(const float4*)(w2 + (size_t)row * HID + 4 * l);
        const float4 hv = *(const float4*)(hs + 4 * l);
        float s = wv.x * hv.x + wv.y * hv.y + wv.z * hv.z + wv.w * hv.w;
#pragma unroll
        for (int o = 16; o > 0; o >>= 1) s += __shfl_xor_sync(0xffffffffu, s, o);
        if (l == 0) raw[row] = s + b2[row];
    }
    __syncthreads();

    // softmax over n for o = t
    float v[NB];
#pragma unroll
    for (int n = 0; n < NB; n++) v[n] = raw[t * NB + n];
    float m = v[0];
#pragma unroll
    for (int n = 1; n < NB; n++) m = fmaxf(m, v[n]);
    float e[NB], s = 0.f;
#pragma unroll
    for (int n = 0; n < NB; n++) { e[n] = expf(v[n] - m); s += e[n]; }
    float inv = 1.f / s;
#pragma unroll
    for (int n = 0; n < NB; n++) g_mix[b * COUT * NB + t * NB + n] = e[n] * inv;
}

// -------- kernel 3: out[b,o,p] = sum_n mix[b,o,n] * y[b,n,p] --------
// Grid: 64 b * 4 o-quarters * 4 pixel-chunks = 1024 CTAs, 256 threads, 4 px/thread.
__global__ __launch_bounds__(256)
void apply_kernel(float* __restrict__ out) {
    __shared__ __align__(16) float ms[64 * NB];
    const int b  = blockIdx.x >> 4;
    const int oq = (blockIdx.x >> 2) & 3;
    const int t  = threadIdx.x;
    const int p0 = (blockIdx.x & 3) * 1024 + t * 4;

    for (int i = t; i < 64 * NB; i += 256)
        ms[i] = g_mix[b * COUT * NB + oq * 64 * NB + i];
    __syncthreads();

    unsigned long long y2[NB][2];
#pragma unroll
    for (int n = 0; n < NB; n++) {
        float4 v = *(const float4*)(g_y + (size_t)(b * NB + n) * HWPIX + p0);
        y2[n][0] = pk2(v.x, v.y);
        y2[n][1] = pk2(v.z, v.w);
    }

    float* ob = out + ((size_t)b * COUT + oq * 64) * HWPIX + p0;
    for (int o = 0; o < 64; o++) {
        const float4 m0 = *(const float4*)(ms + o * NB);
        const float4 m1 = *(const float4*)(ms + o * NB + 4);
        float mv[8] = {m0.x, m0.y, m0.z, m0.w, m1.x, m1.y, m1.z, m1.w};
        unsigned long long a0 = 0ULL, a1 = 0ULL;
#pragma unroll
        for (int n = 0; n < NB; n++) {
            unsigned long long fb = pk2(mv[n], mv[n]);
            a0 = fma2(y2[n][0], fb, a0);
            a1 = fma2(y2[n][1], fb, a1);
        }
        float o0, o1, o2, o3;
        upk2(a0, o0, o1);
        upk2(a1, o2, o3);
        __stcs((float4*)(ob + (size_t)o * HWPIX), make_float4(o0, o1, o2, o3));
    }
}

extern "C" void kernel_launch(void* const* d_in, const int* in_sizes, int n_in,
                              void* d_out, int out_size) {
    const float* x  = (const float*)d_in[0];
    const float* w1 = (const float*)d_in[1];
    const float* b1 = (const float*)d_in[2];
    const float* w2 = (const float*)d_in[3];
    const float* b2 = (const float*)d_in[4];
    const float* bf = (const float*)d_in[5];
    float* out = (float*)d_out;

    const int smem_bytes = FSD_ELEMS * (int)sizeof(float2) + XS_ELEMS * (int)sizeof(float);
    cudaFuncSetAttribute(conv_pool_kernel,
                         cudaFuncAttributeMaxDynamicSharedMemorySize, smem_bytes);

    prep_kernel<<<(CIN * 9 * NB + 255) / 256, 256>>>(bf);
    conv_pool_kernel<<<BB * 4, CONV_THREADS, smem_bytes>>>(x);
    mlp_kernel<<<BB, 256>>>(w1, b1, w2, b2);
    apply_kernel<<<BB * 16, 256>>>(out);
}